// round 1
// baseline (speedup 1.0000x reference)
#include <cuda_runtime.h>

#define DEPTH 8
#define LENGTH 32
#define WIDTH 32
#define NVOX 8192
#define K 8
#define R2 20              // truncate spatial kernel: exp(-21) ~ 7.6e-10, negligible
#define BLK 128
#define NBLK_I (NVOX / BLK)   // 64
#define NDX 9                 // dx in [-4, 4]
#define NPART (NBLK_I * NDX)  // 576

// 16 partial sums per block: [num0..num7, den0..den7]
__device__ float g_part[NPART * 16];

__global__ __launch_bounds__(BLK) void soft_ncuts_pairs(
    const float* __restrict__ patch,
    const float* __restrict__ prob)
{
    const int tid = threadIdx.x;
    const int i = blockIdx.x * BLK + tid;
    const int dx = (int)blockIdx.y - 4;

    const int x = i >> 10;          // i / (32*32)
    const int y = (i >> 5) & 31;
    const int z = i & 31;
    const int xx = x + dx;

    float s[K];
#pragma unroll
    for (int t = 0; t < K; t++) s[t] = 0.0f;
    float sw = 0.0f;

    if (xx >= 0 && xx < DEPTH) {
        const float fi = patch[i];
        const int dx2 = dx * dx;
        const float4* __restrict__ prob4 = reinterpret_cast<const float4*>(prob);

#pragma unroll
        for (int dy = -4; dy <= 4; dy++) {
            const int d2xy = dx2 + dy * dy;
            if (d2xy > R2) continue;
            const int yy = y + dy;
            if (yy < 0 || yy >= LENGTH) continue;
            const int j0 = (xx << 10) + (yy << 5) + z;

#pragma unroll
            for (int dz = -4; dz <= 4; dz++) {
                const int d2 = d2xy + dz * dz;
                if (d2 > R2) continue;
                const int zz = z + dz;
                if (zz < 0 || zz >= WIDTH) continue;
                const int j = j0 + dz;

                const float fj = patch[j];
                const float df = fi - fj;
                // combined exponent: -(d^2 + (df/3)^2)
                const float e = fmaf(df * df, 1.0f / 9.0f, (float)d2);
                const float w = __expf(-e);

                const float4 a = prob4[2 * j];
                const float4 b = prob4[2 * j + 1];
                s[0] = fmaf(w, a.x, s[0]);
                s[1] = fmaf(w, a.y, s[1]);
                s[2] = fmaf(w, a.z, s[2]);
                s[3] = fmaf(w, a.w, s[3]);
                s[4] = fmaf(w, b.x, s[4]);
                s[5] = fmaf(w, b.y, s[5]);
                s[6] = fmaf(w, b.z, s[6]);
                s[7] = fmaf(w, b.w, s[7]);
                sw += w;
            }
        }
    }

    // v[0..7] = P_i[t] * s_t (num contributions), v[8..15] = P_i[t] * sw (den)
    const float4* __restrict__ prob4 = reinterpret_cast<const float4*>(prob);
    const float4 pa = prob4[2 * i];
    const float4 pb = prob4[2 * i + 1];
    float v[16];
    v[0] = pa.x * s[0]; v[1] = pa.y * s[1]; v[2] = pa.z * s[2]; v[3] = pa.w * s[3];
    v[4] = pb.x * s[4]; v[5] = pb.y * s[5]; v[6] = pb.z * s[6]; v[7] = pb.w * s[7];
    v[8]  = pa.x * sw; v[9]  = pa.y * sw; v[10] = pa.z * sw; v[11] = pa.w * sw;
    v[12] = pb.x * sw; v[13] = pb.y * sw; v[14] = pb.z * sw; v[15] = pb.w * sw;

    // warp reduce all 16 values
#pragma unroll
    for (int t = 0; t < 16; t++) {
#pragma unroll
        for (int o = 16; o > 0; o >>= 1)
            v[t] += __shfl_xor_sync(0xFFFFFFFFu, v[t], o);
    }

    __shared__ float red[4][16];
    const int wid = tid >> 5;
    const int lid = tid & 31;
    if (lid == 0) {
#pragma unroll
        for (int t = 0; t < 16; t++) red[wid][t] = v[t];
    }
    __syncthreads();
    if (tid < 16) {
        float acc = red[0][tid] + red[1][tid] + red[2][tid] + red[3][tid];
        g_part[(blockIdx.y * NBLK_I + blockIdx.x) * 16 + tid] = acc;
    }
}

__global__ __launch_bounds__(256) void soft_ncuts_reduce(float* __restrict__ out)
{
    const int tid = threadIdx.x;
    const int c = tid & 15;      // which of the 16 sums
    const int chunk = tid >> 4;  // 16 chunks over 576 partials

    float acc = 0.0f;
    for (int b = chunk; b < NPART; b += 16)
        acc += g_part[b * 16 + c];

    __shared__ float sm[256];
    sm[tid] = acc;
    __syncthreads();

    if (tid < 16) {
        float v = 0.0f;
#pragma unroll
        for (int ch = 0; ch < 16; ch++) v += sm[ch * 16 + tid];
        sm[tid] = v;   // each thread reads only indices ≡ tid (mod 16); self-ordered
    }
    __syncthreads();

    if (tid == 0) {
        float loss = (float)K;
#pragma unroll
        for (int t = 0; t < 8; t++) loss -= sm[t] / sm[8 + t];
        out[0] = loss;
    }
}

extern "C" void kernel_launch(void* const* d_in, const int* in_sizes, int n_in,
                              void* d_out, int out_size)
{
    const float* patch = (const float*)d_in[0];
    const float* prob  = (const float*)d_in[1];
    float* out = (float*)d_out;

    dim3 grid(NBLK_I, NDX);
    soft_ncuts_pairs<<<grid, BLK>>>(patch, prob);
    soft_ncuts_reduce<<<1, 256>>>(out);
}

// round 2
// speedup vs baseline: 1.4717x; 1.4717x over previous
#include <cuda_runtime.h>

#define NVOX 8192
#define K 8
#define BLK 128
#define VPB 64                 // voxels per block
#define NBI (NVOX / VPB)       // 128
#define NDX 4                  // dx in [0,3] (R2=14 -> max |offset| = 3)
#define NPART (NBI * NDX)      // 512 blocks

#define L2E 1.4426950408889634f
#define C1  (L2E / 9.0f)       // log2(e)/std_intensity^2

__device__ float g_part[NPART * 16];
__device__ unsigned int g_count = 0;

// one (dy,dz) pair; D2 is compile-time after unrolling (dx passed as literal)
#define PAIR(D2, DZ) { \
    const int zz = z + (DZ); \
    if ((unsigned)zz < 32u) { \
        const int j = jbase + (DZ); \
        const float df = fi - __ldg(patch + j); \
        const float e2 = fmaf(df * df, -C1, -(float)(D2) * L2E); \
        float w; asm("ex2.approx.f32 %0, %1;" : "=f"(w) : "f"(e2)); \
        const float4 a = __ldg(prob4 + 2 * j); \
        const float4 b = __ldg(prob4 + 2 * j + 1); \
        s0 = fmaf(w, a.x, s0); s1 = fmaf(w, a.y, s1); \
        s2 = fmaf(w, a.z, s2); s3 = fmaf(w, a.w, s3); \
        s4 = fmaf(w, b.x, s4); s5 = fmaf(w, b.y, s5); \
        s6 = fmaf(w, b.z, s6); s7 = fmaf(w, b.w, s7); \
        sw += w; \
    } }

#define ROW(DX, DY, DZLO, DZHI) { \
    const int yy = y + (DY); \
    if ((unsigned)yy < 32u) { \
        const int jbase = jx + (yy << 5) + z; \
        _Pragma("unroll") \
        for (int dzv = (DZLO); dzv <= (DZHI); dzv++) { \
            PAIR((DX) * (DX) + (DY) * (DY) + dzv * dzv, dzv) \
        } \
    } }

__global__ __launch_bounds__(BLK) void soft_ncuts_fused(
    const float* __restrict__ patch,
    const float* __restrict__ prob,
    float* __restrict__ out)
{
    const int tid  = threadIdx.x;
    const int half = tid >> 6;                  // which half of the offset list
    const int i    = blockIdx.x * VPB + (tid & 63);
    const int dx   = blockIdx.y;                // 0..3

    const int y  = (i >> 5) & 31;
    const int z  = i & 31;
    const int xx = (i >> 10) + dx;

    const float4* __restrict__ prob4 = reinterpret_cast<const float4*>(prob);

    float s0 = 0.f, s1 = 0.f, s2 = 0.f, s3 = 0.f;
    float s4 = 0.f, s5 = 0.f, s6 = 0.f, s7 = 0.f, sw = 0.f;

    if (xx < 8) {
        const float fi = __ldg(patch + i);
        const int jx = xx << 10;

        // strictly-positive lexicographic offsets with d^2 <= 14, split into halves
        switch (dx * 2 + half) {
            case 0: ROW(0,  0,  1, 3) ROW(0,  1, -3, 3) break;
            case 1: ROW(0,  2, -3, 3) ROW(0,  3, -2, 2) break;
            case 2: ROW(1, -3, -2, 2) ROW(1, -2, -3, 3)
                    ROW(1, -1, -3, 3) ROW(1,  0, -3, 3) break;
            case 3: ROW(1,  1, -3, 3) ROW(1,  2, -3, 3) ROW(1,  3, -2, 2) break;
            case 4: ROW(2, -3, -1, 1) ROW(2, -2, -2, 2)
                    ROW(2, -1, -3, 3) ROW(2,  0, -3, 3) break;
            case 5: ROW(2,  1, -3, 3) ROW(2,  2, -2, 2) ROW(2,  3, -1, 1) break;
            case 6: ROW(3, -2, -1, 1) ROW(3, -1, -2, 2) ROW(3,  0, -2, 2) break;
            case 7: ROW(3,  1, -2, 2) ROW(3,  2, -1, 1) break;
        }
    }

    // per-thread combine:  num_t += P[t]*(2*s_t + diag*P[t]),
    //                      den_t += P[t]*(sw + diag) + s_t      (diag = self pair, once)
    const float diag = (dx == 0 && half == 0) ? 1.0f : 0.0f;
    const float4 pa = __ldg(prob4 + 2 * i);
    const float4 pb = __ldg(prob4 + 2 * i + 1);

    float v[16];
    v[0] = pa.x * fmaf(diag, pa.x, 2.f * s0);
    v[1] = pa.y * fmaf(diag, pa.y, 2.f * s1);
    v[2] = pa.z * fmaf(diag, pa.z, 2.f * s2);
    v[3] = pa.w * fmaf(diag, pa.w, 2.f * s3);
    v[4] = pb.x * fmaf(diag, pb.x, 2.f * s4);
    v[5] = pb.y * fmaf(diag, pb.y, 2.f * s5);
    v[6] = pb.z * fmaf(diag, pb.z, 2.f * s6);
    v[7] = pb.w * fmaf(diag, pb.w, 2.f * s7);
    const float swd = sw + diag;
    v[8]  = fmaf(pa.x, swd, s0);
    v[9]  = fmaf(pa.y, swd, s1);
    v[10] = fmaf(pa.z, swd, s2);
    v[11] = fmaf(pa.w, swd, s3);
    v[12] = fmaf(pb.x, swd, s4);
    v[13] = fmaf(pb.y, swd, s5);
    v[14] = fmaf(pb.z, swd, s6);
    v[15] = fmaf(pb.w, swd, s7);

    // block reduce 16 values
#pragma unroll
    for (int t = 0; t < 16; t++) {
#pragma unroll
        for (int o = 16; o > 0; o >>= 1)
            v[t] += __shfl_xor_sync(0xFFFFFFFFu, v[t], o);
    }

    __shared__ float sm[128];
    __shared__ unsigned int s_ticket;
    const int wid = tid >> 5, lid = tid & 31;
    if (lid == 0) {
#pragma unroll
        for (int t = 0; t < 16; t++) sm[wid * 16 + t] = v[t];
    }
    __syncthreads();
    if (tid < 16) {
        const float acc = sm[tid] + sm[16 + tid] + sm[32 + tid] + sm[48 + tid];
        g_part[(blockIdx.y * NBI + blockIdx.x) * 16 + tid] = acc;
    }

    // ---- fused finalize: last block reduces all partials ----
    __threadfence();
    __syncthreads();                 // sm reads done; safe to reuse; partials stored
    if (tid == 0) s_ticket = atomicAdd(&g_count, 1u);
    __syncthreads();
    if (s_ticket != NPART - 1) return;

    // deterministic fixed-order reduce of 512 x 16 partials
    const int c = tid & 15;          // which of the 16 sums
    const int chunk = tid >> 4;      // 8 chunks
    float acc = 0.f;
#pragma unroll 8
    for (int b = chunk; b < NPART; b += 8)
        acc += __ldcg(&g_part[b * 16 + c]);
    sm[tid] = acc;
    __syncthreads();
    if (tid < 16) {
        float t0 = 0.f;
#pragma unroll
        for (int ch = 0; ch < 8; ch++) t0 += sm[ch * 16 + tid];
        sm[tid] = t0;                // lane-exclusive slot, no race
    }
    __syncthreads();
    if (tid == 0) {
        float loss = (float)K;
#pragma unroll
        for (int t = 0; t < 8; t++) loss -= sm[t] / sm[8 + t];
        out[0] = loss;
        g_count = 0;                 // reset for next graph replay
    }
}

extern "C" void kernel_launch(void* const* d_in, const int* in_sizes, int n_in,
                              void* d_out, int out_size)
{
    const float* patch = (const float*)d_in[0];
    const float* prob  = (const float*)d_in[1];
    float* out = (float*)d_out;

    dim3 grid(NBI, NDX);
    soft_ncuts_fused<<<grid, BLK>>>(patch, prob, out);
}

// round 3
// speedup vs baseline: 1.4975x; 1.0175x over previous
#include <cuda_runtime.h>

#define NVOX 8192
#define K 8
#define BLK 128
#define VPB 64                 // voxels per block
#define NBI (NVOX / VPB)       // 128
#define NCY 8                  // blockIdx.y
#define NBLK (NBI * NCY)       // 1024 blocks; 16 cases via half-split
#define L2E 1.4426950408889634f
#define C1  (L2E / 9.0f)

__device__ float g_part[16 * NBLK];     // transposed: [component][block]
__device__ unsigned int g_count = 0;

#define PAIR(D2, DZ) { \
    const int zz = z + (DZ); \
    if ((unsigned)zz < 32u) { \
        const int j = jbase + (DZ); \
        const float df = fi - __ldg(patch + j); \
        const float e2 = fmaf(df * df, -C1, -(float)(D2) * L2E); \
        float w; asm("ex2.approx.f32 %0, %1;" : "=f"(w) : "f"(e2)); \
        const float4 a = __ldg(prob4 + 2 * j); \
        const float4 b = __ldg(prob4 + 2 * j + 1); \
        s0 = fmaf(w, a.x, s0); s1 = fmaf(w, a.y, s1); \
        s2 = fmaf(w, a.z, s2); s3 = fmaf(w, a.w, s3); \
        s4 = fmaf(w, b.x, s4); s5 = fmaf(w, b.y, s5); \
        s6 = fmaf(w, b.z, s6); s7 = fmaf(w, b.w, s7); \
        sw += w; \
    } }

#define ROW(DX, DY, DZLO, DZHI) { \
    const int yy = y + (DY); \
    const int xx = x + (DX); \
    if ((unsigned)yy < 32u && xx < 8) { \
        const int jbase = (xx << 10) + (yy << 5) + z; \
        _Pragma("unroll") \
        for (int dzv = (DZLO); dzv <= (DZHI); dzv++) { \
            PAIR((DX) * (DX) + (DY) * (DY) + dzv * dzv, dzv) \
        } \
    } }

__global__ __launch_bounds__(BLK) void soft_ncuts_fused(
    const float* __restrict__ patch,
    const float* __restrict__ prob,
    float* __restrict__ out)
{
    const int tid  = threadIdx.x;
    const int half = tid >> 6;
    const int i    = blockIdx.x * VPB + (tid & 63);
    const int cse  = (int)blockIdx.y * 2 + half;   // 0..15, balanced 7-8 pairs

    const int x = i >> 10;
    const int y = (i >> 5) & 31;
    const int z = i & 31;

    const float4* __restrict__ prob4 = reinterpret_cast<const float4*>(prob);
    const float fi = __ldg(patch + i);

    float s0 = 0.f, s1 = 0.f, s2 = 0.f, s3 = 0.f;
    float s4 = 0.f, s5 = 0.f, s6 = 0.f, s7 = 0.f, sw = 0.f;

    // 125 strictly-positive offsets (d^2 <= 14) in 16 balanced chunks
    switch (cse) {
        case  0: ROW(0,0,1,3)    ROW(0,3,-2,2)               break; // 8
        case  1: ROW(0,1,-3,3)                               break; // 7
        case  2: ROW(0,2,-3,3)                               break; // 7
        case  3: ROW(1,-3,-2,2)  ROW(1,-2,-3,-1)             break; // 8
        case  4: ROW(1,-2,0,3)   ROW(1,-1,-3,0)              break; // 8
        case  5: ROW(1,-1,1,3)   ROW(1,0,-3,1)               break; // 8
        case  6: ROW(1,0,2,3)    ROW(1,1,-3,2)               break; // 8
        case  7: ROW(1,1,3,3)    ROW(1,2,-3,3)               break; // 8
        case  8: ROW(1,3,-2,2)   ROW(2,-3,-1,1)              break; // 8
        case  9: ROW(2,-2,-2,2)  ROW(2,-1,-3,-1)             break; // 8
        case 10: ROW(2,-1,0,3)   ROW(2,0,-3,0)               break; // 8
        case 11: ROW(2,0,1,3)    ROW(2,1,-3,1)               break; // 8
        case 12: ROW(2,1,2,3)    ROW(2,2,-2,2)               break; // 7
        case 13: ROW(2,3,-1,1)   ROW(3,-2,-1,1) ROW(3,-1,-2,-1) break; // 8
        case 14: ROW(3,-1,0,2)   ROW(3,0,-2,2)               break; // 8
        case 15: ROW(3,1,-2,2)   ROW(3,2,-1,1)               break; // 8
    }

    // per-thread combine (symmetry: num += P*(2s + diag*P), den += P*(sw+diag) + s)
    const float diag = (cse == 0) ? 1.0f : 0.0f;
    const float4 pa = __ldg(prob4 + 2 * i);
    const float4 pb = __ldg(prob4 + 2 * i + 1);

    float v[16];
    v[0] = pa.x * fmaf(diag, pa.x, 2.f * s0);
    v[1] = pa.y * fmaf(diag, pa.y, 2.f * s1);
    v[2] = pa.z * fmaf(diag, pa.z, 2.f * s2);
    v[3] = pa.w * fmaf(diag, pa.w, 2.f * s3);
    v[4] = pb.x * fmaf(diag, pb.x, 2.f * s4);
    v[5] = pb.y * fmaf(diag, pb.y, 2.f * s5);
    v[6] = pb.z * fmaf(diag, pb.z, 2.f * s6);
    v[7] = pb.w * fmaf(diag, pb.w, 2.f * s7);
    const float swd = sw + diag;
    v[8]  = fmaf(pa.x, swd, s0);
    v[9]  = fmaf(pa.y, swd, s1);
    v[10] = fmaf(pa.z, swd, s2);
    v[11] = fmaf(pa.w, swd, s3);
    v[12] = fmaf(pb.x, swd, s4);
    v[13] = fmaf(pb.y, swd, s5);
    v[14] = fmaf(pb.z, swd, s6);
    v[15] = fmaf(pb.w, swd, s7);

    const int lid = tid & 31, wid = tid >> 5;

    // packed multi-value warp reduction: 31 shuffles instead of 80
#pragma unroll
    for (int t = 0; t < 16; t++) v[t] += __shfl_xor_sync(0xFFFFFFFFu, v[t], 16);
    float u[8];
#pragma unroll
    for (int t = 0; t < 8; t++) {
        u[t] = (lid & 16) ? v[t + 8] : v[t];
        u[t] += __shfl_xor_sync(0xFFFFFFFFu, u[t], 8);
    }
    float w4[4];
#pragma unroll
    for (int t = 0; t < 4; t++) {
        w4[t] = (lid & 8) ? u[t + 4] : u[t];
        w4[t] += __shfl_xor_sync(0xFFFFFFFFu, w4[t], 4);
    }
    float y2[2];
#pragma unroll
    for (int t = 0; t < 2; t++) {
        y2[t] = (lid & 4) ? w4[t + 2] : w4[t];
        y2[t] += __shfl_xor_sync(0xFFFFFFFFu, y2[t], 2);
    }
    float z1 = (lid & 2) ? y2[1] : y2[0];
    z1 += __shfl_xor_sync(0xFFFFFFFFu, z1, 1);
    // lane 2t (and 2t+1) now holds the warp total of v[t]

    __shared__ float sm[128];
    __shared__ unsigned int s_ticket;
    if (!(lid & 1)) sm[wid * 16 + (lid >> 1)] = z1;
    __syncthreads();

    const int gb = (int)blockIdx.y * NBI + (int)blockIdx.x;   // 0..1023
    if (tid < 16) {
        const float acc = sm[tid] + sm[16 + tid] + sm[32 + tid] + sm[48 + tid];
        g_part[tid * NBLK + gb] = acc;                        // transposed layout
    }

    // ---- fused finalize ----
    __threadfence();
    __syncthreads();
    if (tid == 0) s_ticket = atomicAdd(&g_count, 1u);
    __syncthreads();
    if (s_ticket != NBLK - 1) return;
    __threadfence();

    // 16 components x 8 chunks; contiguous float4 reads, fixed order
    {
        const int c = tid >> 3;          // 0..15
        const int chunk = tid & 7;       // 0..7
        const float4* __restrict__ gp4 =
            reinterpret_cast<const float4*>(g_part) + (c * NBLK + chunk * 128) / 4;
        float ax = 0.f, ay = 0.f, az = 0.f, aw = 0.f;
#pragma unroll
        for (int k2 = 0; k2 < 32; k2++) {
            const float4 p = __ldcg(gp4 + k2);
            ax += p.x; ay += p.y; az += p.z; aw += p.w;
        }
        sm[tid] = (ax + ay) + (az + aw);
    }
    __syncthreads();
    if (tid < 16) {
        float t0 = 0.f;
#pragma unroll
        for (int ch = 0; ch < 8; ch++) t0 += sm[tid * 8 + ch];
        sm[tid] = t0;                    // lane-exclusive slot
    }
    __syncthreads();
    if (tid == 0) {
        float loss = (float)K;
#pragma unroll
        for (int t = 0; t < 8; t++) loss -= sm[t] / sm[8 + t];
        out[0] = loss;
        g_count = 0;                     // reset for graph replay
    }
}

extern "C" void kernel_launch(void* const* d_in, const int* in_sizes, int n_in,
                              void* d_out, int out_size)
{
    const float* patch = (const float*)d_in[0];
    const float* prob  = (const float*)d_in[1];
    float* out = (float*)d_out;

    dim3 grid(NBI, NCY);
    soft_ncuts_fused<<<grid, BLK>>>(patch, prob, out);
}

// round 4
// speedup vs baseline: 1.5013x; 1.0025x over previous
#include <cuda_runtime.h>

#define K 8
#define BLK 576                 // 18 warps = 18 offset chunks
#define NBLK 256                // one block per (x,y) row
#define L2E 1.4426950408889634f
#define C1  (L2E / 9.0f)

__device__ float g_part[16 * NBLK];   // transposed [component][block]
__device__ unsigned int g_count = 0;

#define FULL 0xFFFFFFFFu

// One neighbor row (DX,DY): 3 coalesced loads, then DZ pairs via shuffles only.
#define ROWS(DX, DY, DZLO, DZHI) { \
    const int xx = x + (DX); \
    const int yy = y + (DY); \
    if (xx < 8 && (unsigned)yy < 32u) {   /* warp-uniform branch */ \
        const int jr = (xx << 10) + (yy << 5) + lane; \
        const float fj = __ldg(patch + jr); \
        const float4 qa = __ldg(prob4 + 2 * jr); \
        const float4 qb = __ldg(prob4 + 2 * jr + 1); \
        _Pragma("unroll") \
        for (int dz = (DZLO); dz <= (DZHI); dz++) { \
            const int src = lane + dz; \
            const int sm5 = src & 31; \
            const float fjn = __shfl_sync(FULL, fj, sm5); \
            const float df = fi - fjn; \
            const float e2 = fmaf(df * df, -C1, \
                -(float)((DX)*(DX) + (DY)*(DY) + dz*dz) * L2E); \
            float w; asm("ex2.approx.f32 %0, %1;" : "=f"(w) : "f"(e2)); \
            w = ((unsigned)src < 32u) ? w : 0.0f; \
            s0 = fmaf(w, __shfl_sync(FULL, qa.x, sm5), s0); \
            s1 = fmaf(w, __shfl_sync(FULL, qa.y, sm5), s1); \
            s2 = fmaf(w, __shfl_sync(FULL, qa.z, sm5), s2); \
            s3 = fmaf(w, __shfl_sync(FULL, qa.w, sm5), s3); \
            s4 = fmaf(w, __shfl_sync(FULL, qb.x, sm5), s4); \
            s5 = fmaf(w, __shfl_sync(FULL, qb.y, sm5), s5); \
            s6 = fmaf(w, __shfl_sync(FULL, qb.z, sm5), s6); \
            s7 = fmaf(w, __shfl_sync(FULL, qb.w, sm5), s7); \
            sw += w; \
        } \
    } }

__global__ __launch_bounds__(BLK) void soft_ncuts_fused(
    const float* __restrict__ patch,
    const float* __restrict__ prob,
    float* __restrict__ out)
{
    const int tid   = threadIdx.x;
    const int lane  = tid & 31;          // = z
    const int chunk = tid >> 5;          // 0..17
    const int x = (int)blockIdx.x >> 5;  // 0..7
    const int y = (int)blockIdx.x & 31;  // 0..31
    const int i = (x << 10) + (y << 5) + lane;

    const float4* __restrict__ prob4 = reinterpret_cast<const float4*>(prob);
    const float fi = __ldg(patch + i);

    float s0 = 0.f, s1 = 0.f, s2 = 0.f, s3 = 0.f;
    float s4 = 0.f, s5 = 0.f, s6 = 0.f, s7 = 0.f, sw = 0.f;

    // 125 strictly-positive offsets (d^2 <= 14) in 18 balanced chunks
    switch (chunk) {
        case  0: ROWS(0,0,1,3)    ROWS(0,3,-2,2)   break; // 8  [diag chunk]
        case  1: ROWS(0,1,-3,3)                    break; // 7
        case  2: ROWS(0,2,-3,3)                    break; // 7
        case  3: ROWS(1,-2,-3,3)                   break; // 7
        case  4: ROWS(1,-1,-3,3)                   break; // 7
        case  5: ROWS(1,0,-3,3)                    break; // 7
        case  6: ROWS(1,1,-3,3)                    break; // 7
        case  7: ROWS(1,2,-3,3)                    break; // 7
        case  8: ROWS(2,-1,-3,3)                   break; // 7
        case  9: ROWS(2,0,-3,3)                    break; // 7
        case 10: ROWS(2,1,-3,3)                    break; // 7
        case 11: ROWS(1,-3,-2,2)  ROWS(2,-3,-1,1)  break; // 8
        case 12: ROWS(1,3,-2,2)   ROWS(2,3,-1,1)   break; // 8
        case 13: ROWS(3,-2,-1,1)  ROWS(3,-1,-2,2)  break; // 8
        case 14: ROWS(3,2,-1,1)   ROWS(3,1,-2,2)   break; // 8
        case 15: ROWS(2,-2,-2,2)                   break; // 5
        case 16: ROWS(2,2,-2,2)                    break; // 5
        case 17: ROWS(3,0,-2,2)                    break; // 5
    }

    // per-thread combine (symmetry: num += P*(2s + diag*P), den += P*(sw+diag) + s)
    const float diag = (chunk == 0) ? 1.0f : 0.0f;
    const float4 pa = __ldg(prob4 + 2 * i);
    const float4 pb = __ldg(prob4 + 2 * i + 1);

    float v[16];
    v[0] = pa.x * fmaf(diag, pa.x, 2.f * s0);
    v[1] = pa.y * fmaf(diag, pa.y, 2.f * s1);
    v[2] = pa.z * fmaf(diag, pa.z, 2.f * s2);
    v[3] = pa.w * fmaf(diag, pa.w, 2.f * s3);
    v[4] = pb.x * fmaf(diag, pb.x, 2.f * s4);
    v[5] = pb.y * fmaf(diag, pb.y, 2.f * s5);
    v[6] = pb.z * fmaf(diag, pb.z, 2.f * s6);
    v[7] = pb.w * fmaf(diag, pb.w, 2.f * s7);
    const float swd = sw + diag;
    v[8]  = fmaf(pa.x, swd, s0);
    v[9]  = fmaf(pa.y, swd, s1);
    v[10] = fmaf(pa.z, swd, s2);
    v[11] = fmaf(pa.w, swd, s3);
    v[12] = fmaf(pb.x, swd, s4);
    v[13] = fmaf(pb.y, swd, s5);
    v[14] = fmaf(pb.z, swd, s6);
    v[15] = fmaf(pb.w, swd, s7);

    // packed multi-value warp reduction (31 shuffles)
#pragma unroll
    for (int t = 0; t < 16; t++) v[t] += __shfl_xor_sync(FULL, v[t], 16);
    float u[8];
#pragma unroll
    for (int t = 0; t < 8; t++) {
        u[t] = (lane & 16) ? v[t + 8] : v[t];
        u[t] += __shfl_xor_sync(FULL, u[t], 8);
    }
    float w4[4];
#pragma unroll
    for (int t = 0; t < 4; t++) {
        w4[t] = (lane & 8) ? u[t + 4] : u[t];
        w4[t] += __shfl_xor_sync(FULL, w4[t], 4);
    }
    float y2[2];
#pragma unroll
    for (int t = 0; t < 2; t++) {
        y2[t] = (lane & 4) ? w4[t + 2] : w4[t];
        y2[t] += __shfl_xor_sync(FULL, y2[t], 2);
    }
    float z1 = (lane & 2) ? y2[1] : y2[0];
    z1 += __shfl_xor_sync(FULL, z1, 1);
    // lanes 2t, 2t+1 hold the warp total of v[t]

    __shared__ float sm[18 * 16];
    __shared__ unsigned int s_ticket;
    if (!(lane & 1)) sm[chunk * 16 + (lane >> 1)] = z1;
    __syncthreads();

    if (tid < 16) {
        float acc = 0.f;
#pragma unroll
        for (int wch = 0; wch < 18; wch++) acc += sm[wch * 16 + tid];
        g_part[tid * NBLK + (int)blockIdx.x] = acc;
    }

    // ---- fused finalize: last block reduces 16 x 256 partials ----
    __threadfence();
    __syncthreads();
    if (tid == 0) s_ticket = atomicAdd(&g_count, 1u);
    __syncthreads();
    if (s_ticket != NBLK - 1) return;
    __threadfence();

    if (tid < 512) {
        const int c  = tid >> 5;        // component 0..15 (warp c)
        const int sg = tid & 31;
        const float4* __restrict__ g4 =
            reinterpret_cast<const float4*>(g_part) + c * 64 + sg * 2;
        const float4 p = __ldcg(g4);
        const float4 q = __ldcg(g4 + 1);
        float a = ((p.x + p.y) + (p.z + p.w)) + ((q.x + q.y) + (q.z + q.w));
#pragma unroll
        for (int o = 16; o > 0; o >>= 1) a += __shfl_xor_sync(FULL, a, o);
        if (sg == 0) sm[c] = a;
    }
    __syncthreads();
    if (tid == 0) {
        float loss = (float)K;
#pragma unroll
        for (int t = 0; t < 8; t++) loss -= sm[t] / sm[8 + t];
        out[0] = loss;
        g_count = 0;                    // reset for graph replay
    }
}

extern "C" void kernel_launch(void* const* d_in, const int* in_sizes, int n_in,
                              void* d_out, int out_size)
{
    const float* patch = (const float*)d_in[0];
    const float* prob  = (const float*)d_in[1];
    float* out = (float*)d_out;

    soft_ncuts_fused<<<NBLK, BLK>>>(patch, prob, out);
}